// round 3
// baseline (speedup 1.0000x reference)
#include <cuda_runtime.h>
#include <cstdint>

// Problem constants
#define Bc   4
#define Sc   2048
#define Ec   1024
#define Hc   16
#define Dc   64
#define WINc 512
#define E3c  3072
#define NTOK 8192   // B*S

// Scratch (device globals: allocation-free per harness rules)
__device__ float g_qkv[(size_t)NTOK * E3c];  // [tok, 3E]  (q | k | v)
__device__ float g_o[(size_t)NTOK * Ec];     // [tok, E] attention output

// ---------------------------------------------------------------------------
// helpers
// ---------------------------------------------------------------------------
__device__ __forceinline__ float cvt_tf32(float x) {
    unsigned u;
    asm("cvt.rna.tf32.f32 %0, %1;" : "=r"(u) : "f"(x));
    return __uint_as_float(u);
}

__device__ __forceinline__ void mma_tf32(float* c, const unsigned* a, const unsigned* b) {
    asm volatile(
        "mma.sync.aligned.m16n8k8.row.col.f32.tf32.tf32.f32 "
        "{%0,%1,%2,%3}, {%4,%5,%6,%7}, {%8,%9}, {%0,%1,%2,%3};"
        : "+f"(c[0]), "+f"(c[1]), "+f"(c[2]), "+f"(c[3])
        : "r"(a[0]), "r"(a[1]), "r"(a[2]), "r"(a[3]), "r"(b[0]), "r"(b[1]));
}

typedef unsigned long long u64;

__device__ __forceinline__ u64 pack2(float lo, float hi) {
    u64 r;
    asm("mov.b64 %0, {%1,%2};" : "=l"(r) : "f"(lo), "f"(hi));
    return r;
}
__device__ __forceinline__ void unpack2(u64 v, float& lo, float& hi) {
    asm("mov.b64 {%0,%1}, %2;" : "=f"(lo), "=f"(hi) : "l"(v));
}
__device__ __forceinline__ u64 ffma2(u64 a, u64 b, u64 c) {
    u64 d;
    asm("fma.rn.f32x2 %0, %1, %2, %3;" : "=l"(d) : "l"(a), "l"(b), "l"(c));
    return d;
}
__device__ __forceinline__ u64 fmul2(u64 a, u64 b) {
    u64 d;
    asm("mul.rn.f32x2 %0, %1, %2;" : "=l"(d) : "l"(a), "l"(b));
    return d;
}

// ---------------------------------------------------------------------------
// NT GEMM (tf32 tensor cores): C[M,N] = A[M,K] * B[N,K]^T, all row-major fp32.
// BM=BN=128, BK=32, 256 threads, 8 warps each computing 64x32.
// ---------------------------------------------------------------------------
#define LDT 36  // smem row stride (32 + 4): frag loads bank-conflict-free

__global__ __launch_bounds__(256, 2)
void gemm_nt_tf32(const float* __restrict__ A, const float* __restrict__ Bm,
                  float* __restrict__ C, int M, int N, int K) {
    __shared__ float sA[128 * LDT];
    __shared__ float sB[128 * LDT];

    const int tid  = threadIdx.x;
    const int lane = tid & 31;
    const int warp = tid >> 5;
    const int wm   = (warp & 1) * 64;   // warp m-offset within block
    const int wn   = (warp >> 1) * 32;  // warp n-offset within block
    const int bm   = blockIdx.y;
    const int bn   = blockIdx.x;
    const int nk   = K >> 5;

    float c[4][4][4];
#pragma unroll
    for (int mi = 0; mi < 4; mi++)
#pragma unroll
        for (int ni = 0; ni < 4; ni++)
#pragma unroll
            for (int r = 0; r < 4; r++) c[mi][ni][r] = 0.0f;

    // register-staged loads (overlap next tile's LDG with current compute)
    float4 ra[4], rb[4];
#pragma unroll
    for (int i = 0; i < 4; i++) {
        int f = tid + i * 256;
        int row = f >> 3, c4 = f & 7;
        ra[i] = *(const float4*)(A + (size_t)(bm * 128 + row) * K + c4 * 4);
        rb[i] = *(const float4*)(Bm + (size_t)(bn * 128 + row) * K + c4 * 4);
    }

    for (int kb = 0;;) {
        // store staged tile (with rna tf32 rounding)
#pragma unroll
        for (int i = 0; i < 4; i++) {
            int f = tid + i * 256;
            int row = f >> 3, c4 = f & 7;
            float* p = &sA[row * LDT + c4 * 4];
            p[0] = cvt_tf32(ra[i].x); p[1] = cvt_tf32(ra[i].y);
            p[2] = cvt_tf32(ra[i].z); p[3] = cvt_tf32(ra[i].w);
            float* q = &sB[row * LDT + c4 * 4];
            q[0] = cvt_tf32(rb[i].x); q[1] = cvt_tf32(rb[i].y);
            q[2] = cvt_tf32(rb[i].z); q[3] = cvt_tf32(rb[i].w);
        }
        __syncthreads();

        if (kb + 1 < nk) {
#pragma unroll
            for (int i = 0; i < 4; i++) {
                int f = tid + i * 256;
                int row = f >> 3, c4 = f & 7;
                ra[i] = *(const float4*)(A + (size_t)(bm * 128 + row) * K + (kb + 1) * 32 + c4 * 4);
                rb[i] = *(const float4*)(Bm + (size_t)(bn * 128 + row) * K + (kb + 1) * 32 + c4 * 4);
            }
        }

#pragma unroll
        for (int kk = 0; kk < 4; kk++) {
            const int k0 = kk * 8;
            unsigned afr[4][4], bfr[4][2];
#pragma unroll
            for (int mi = 0; mi < 4; mi++) {
                int r0 = wm + mi * 16 + (lane >> 2);
                int cc = k0 + (lane & 3);
                afr[mi][0] = __float_as_uint(sA[r0 * LDT + cc]);
                afr[mi][1] = __float_as_uint(sA[(r0 + 8) * LDT + cc]);
                afr[mi][2] = __float_as_uint(sA[r0 * LDT + cc + 4]);
                afr[mi][3] = __float_as_uint(sA[(r0 + 8) * LDT + cc + 4]);
            }
#pragma unroll
            for (int ni = 0; ni < 4; ni++) {
                int rn = wn + ni * 8 + (lane >> 2);
                int cc = k0 + (lane & 3);
                bfr[ni][0] = __float_as_uint(sB[rn * LDT + cc]);
                bfr[ni][1] = __float_as_uint(sB[rn * LDT + cc + 4]);
            }
#pragma unroll
            for (int mi = 0; mi < 4; mi++)
#pragma unroll
                for (int ni = 0; ni < 4; ni++) mma_tf32(c[mi][ni], afr[mi], bfr[ni]);
        }
        __syncthreads();
        if (++kb == nk) break;
    }

    // epilogue
#pragma unroll
    for (int mi = 0; mi < 4; mi++) {
        int row = bm * 128 + wm + mi * 16 + (lane >> 2);
#pragma unroll
        for (int ni = 0; ni < 4; ni++) {
            int col = bn * 128 + wn + ni * 8 + 2 * (lane & 3);
            C[(size_t)row * N + col]           = c[mi][ni][0];
            C[(size_t)row * N + col + 1]       = c[mi][ni][1];
            C[(size_t)(row + 8) * N + col]     = c[mi][ni][2];
            C[(size_t)(row + 8) * N + col + 1] = c[mi][ni][3];
        }
    }
}

// ---------------------------------------------------------------------------
// Sliding-window attention with ALiBi, flash-style, one thread = one query.
// Block = 128 queries for one (b, h). Q + accumulator packed as f32x2 pairs,
// K/V streamed through smem in 64-key chunks (broadcast LDS.128).
// Branch-free online softmax over 8-key batches:
//   masked score -> -1e30 (SEL), m init -1e29 so all-masked batches give p=0.
// scores = (q.k)/8 + slope*(q_idx - kv_idx), mask 0 <= q_idx - kv_idx <= 512.
// ---------------------------------------------------------------------------
__global__ __launch_bounds__(128, 2)
void attn_kernel() {
    __shared__ float sm[8704];  // Q/out staging (128*68); K@0, V@4096 (stride 64)

    const int tid = threadIdx.x;
    const int qt  = blockIdx.x;
    const int h   = blockIdx.y;
    const int b   = blockIdx.z;
    const int qstart = qt * 128;

    // ---- stage Q tile (coalesced) then copy own row into packed regs ----
    const size_t base_q = (size_t)(b * Sc + qstart) * E3c + h * Dc;
#pragma unroll
    for (int i = 0; i < 16; i++) {
        int f = tid + i * 128;
        int ql = f >> 4, c4 = f & 15;
        *(float4*)&sm[ql * 68 + c4 * 4] =
            *(const float4*)(g_qkv + base_q + (size_t)ql * E3c + c4 * 4);
    }
    __syncthreads();

    u64 q2[32];
#pragma unroll
    for (int j = 0; j < 32; j++) q2[j] = *(const u64*)&sm[tid * 68 + 2 * j];
    __syncthreads();

    u64 acc2[32];
#pragma unroll
    for (int j = 0; j < 32; j++) acc2[j] = 0ull;
    float m = -1e29f, l = 0.0f;

    const int   qpos  = qstart + tid;
    const int   q0w   = qstart + (tid & ~31);  // warp's first query position
    const float slope = exp2f(-(float)(h + 1) * 0.5f);

    int kb0 = qstart - WINc;
    if (kb0 < 0) kb0 = 0;

    for (int kb = kb0; kb < qstart + 128; kb += 64) {
        // load K and V chunks [64][64] (coalesced)
#pragma unroll
        for (int i = 0; i < 8; i++) {
            int f = tid + i * 128;
            int r = f >> 4, c4 = f & 15;
            size_t gb = (size_t)(b * Sc + kb + r) * E3c + h * Dc + c4 * 4;
            *(float4*)&sm[r * 64 + c4 * 4]        = *(const float4*)(g_qkv + gb + Ec);
            *(float4*)&sm[4096 + r * 64 + c4 * 4] = *(const float4*)(g_qkv + gb + 2 * Ec);
        }
        __syncthreads();

        // warp-uniform batch range (no intra-warp loop-bound divergence)
        int wjlo = q0w - WINc - kb;  if (wjlo < 0) wjlo = 0;
        int wjhi = q0w + 31 - kb;    if (wjhi > 63) wjhi = 63;

        for (int j0 = wjlo & ~7; j0 <= wjhi; j0 += 8) {
            // ---- scores for 8 keys: 4 independent ffma2 chains each ----
            float s[8];
#pragma unroll
            for (int i = 0; i < 8; i++) {
                const ulonglong2* kp = (const ulonglong2*)&sm[(j0 + i) * 64];
                u64 c0 = 0ull, c1 = 0ull, c2c = 0ull, c3 = 0ull;
#pragma unroll
                for (int jj = 0; jj < 8; jj++) {
                    ulonglong2 ka = kp[2 * jj];
                    ulonglong2 kb2 = kp[2 * jj + 1];
                    c0  = ffma2(q2[4 * jj + 0], ka.x,  c0);
                    c1  = ffma2(q2[4 * jj + 1], ka.y,  c1);
                    c2c = ffma2(q2[4 * jj + 2], kb2.x, c2c);
                    c3  = ffma2(q2[4 * jj + 3], kb2.y, c3);
                }
                float a0, a1, b0, b1, e0, e1, d0, d1;
                unpack2(c0, a0, a1); unpack2(c1, b0, b1);
                unpack2(c2c, e0, e1); unpack2(c3, d0, d1);
                float dot = ((a0 + b0) + (a1 + b1)) + ((e0 + d0) + (e1 + d1));
                int delta = qpos - (kb + j0 + i);
                float sv = dot * 0.125f + slope * (float)delta;
                s[i] = ((unsigned)delta <= (unsigned)WINc) ? sv : -1e30f;
            }

            // ---- branch-free online softmax update ----
            float m01 = fmaxf(s[0], s[1]), m23 = fmaxf(s[2], s[3]);
            float m45 = fmaxf(s[4], s[5]), m67 = fmaxf(s[6], s[7]);
            float bmax = fmaxf(fmaxf(m01, m23), fmaxf(m45, m67));
            float mnew = fmaxf(m, bmax);
            float corr = __expf(m - mnew);
            m = mnew;

            float p[8];
#pragma unroll
            for (int i = 0; i < 8; i++) p[i] = __expf(s[i] - mnew);
            float ps = ((p[0] + p[1]) + (p[2] + p[3])) + ((p[4] + p[5]) + (p[6] + p[7]));
            l = l * corr + ps;

            u64 cc2 = pack2(corr, corr);
#pragma unroll
            for (int jj = 0; jj < 32; jj++) acc2[jj] = fmul2(acc2[jj], cc2);

            // ---- PV accumulate: 8 keys ----
#pragma unroll
            for (int i = 0; i < 8; i++) {
                u64 p2 = pack2(p[i], p[i]);
                const ulonglong2* vp = (const ulonglong2*)&sm[4096 + (j0 + i) * 64];
#pragma unroll
                for (int jj = 0; jj < 16; jj++) {
                    ulonglong2 v01 = vp[jj];
                    acc2[2 * jj]     = ffma2(p2, v01.x, acc2[2 * jj]);
                    acc2[2 * jj + 1] = ffma2(p2, v01.y, acc2[2 * jj + 1]);
                }
            }
        }
        __syncthreads();
    }

    // ---- normalize, stage to smem, coalesced store to g_o [tok, E] ----
    float inv = 1.0f / l;
#pragma unroll
    for (int jj = 0; jj < 32; jj++) {
        float a0, a1;
        unpack2(acc2[jj], a0, a1);
        sm[tid * 68 + 2 * jj]     = a0 * inv;
        sm[tid * 68 + 2 * jj + 1] = a1 * inv;
    }
    __syncthreads();

    const size_t base_o = (size_t)(b * Sc + qstart) * Ec + h * Dc;
#pragma unroll
    for (int i = 0; i < 16; i++) {
        int f = tid + i * 128;
        int ql = f >> 4, c4 = f & 15;
        *(float4*)(g_o + base_o + (size_t)ql * Ec + c4 * 4) =
            *(const float4*)&sm[ql * 68 + c4 * 4];
    }
}

// ---------------------------------------------------------------------------
// launch
// ---------------------------------------------------------------------------
extern "C" void kernel_launch(void* const* d_in, const int* in_sizes, int n_in,
                              void* d_out, int out_size) {
    const float* x     = (const float*)d_in[0];  // [B,S,E]
    const float* w_in  = (const float*)d_in[1];  // [3E,E]
    const float* w_out = (const float*)d_in[2];  // [E,E]
    float* out = (float*)d_out;                  // [B,S,E]

    float *qkv_ptr, *o_ptr;
    cudaGetSymbolAddress((void**)&qkv_ptr, g_qkv);
    cudaGetSymbolAddress((void**)&o_ptr, g_o);

    // 1) qkv = x @ w_in^T   : [8192,3072]
    gemm_nt_tf32<<<dim3(E3c / 128, NTOK / 128), 256>>>(x, w_in, qkv_ptr, NTOK, E3c, Ec);
    // 2) sliding-window attention -> g_o [8192,1024]
    attn_kernel<<<dim3(Sc / 128, Hc, Bc), 128>>>();
    // 3) out = o @ w_out^T  : [8192,1024]
    gemm_nt_tf32<<<dim3(Ec / 128, NTOK / 128), 256>>>(o_ptr, w_out, out, NTOK, Ec, Ec);
}